// round 12
// baseline (speedup 1.0000x reference)
#include <cuda_runtime.h>
#include <math.h>

// Problem constants (fixed by the reference: B=16, N=4096, Z=128)
#define BB 16
#define NN 4096
#define ZZ 128

#define THREADS 512
#define Q 4                     // preds per thread: 512*4 = 2048 = HALF the batch's preds
#define HALF 2048
#define NCTA 444                // 3 CTAs/SM on 148 SMs: all co-resident -> barrier safe
#define GTSMAX 320              // max gt-chunk (<=316 actual, padded)
#define NKEYS (BB * NN)         // 65536

// Encoded min keys: zero-init == identity for atomicMax == +inf in min-space.
__device__ unsigned g_rmkey[NKEYS];     // row-mins (per pred), 256KB L2-resident
__device__ unsigned g_cmkey[NKEYS];     // col-mins (per gt),   256KB L2-resident
__device__ float    g_part2[NCTA];
__device__ int      g_c1 = 0;
__device__ int      g_c2 = 0;

// Monotone-DECREASING float->uint map (min(v) <=> max(key)), identity 0.
__device__ __forceinline__ unsigned enc_min(float v) {
    unsigned b = __float_as_uint(v);
    return (b & 0x80000000u) ? b : (~b & 0x7FFFFFFFu);
}
__device__ __forceinline__ float dec_min(unsigned m) {
    return __uint_as_float((m & 0x80000000u) ? m : (~m & 0x7FFFFFFFu));
}

// Warp-wide max reduction in ONE instruction.
__device__ __forceinline__ unsigned warp_redux_max(unsigned v) {
    unsigned r;
    asm("redux.sync.max.u32 %0, %1, 0xffffffff;" : "=r"(r) : "r"(v));
    return r;
}

// FFMA with immediate 1.0 multiplier: rt_SMSP=1
__device__ __forceinline__ float fma_i1(float a, float c) {
    float d;
    asm("fma.rn.f32 %0, %1, 0f3F800000, %2;" : "=f"(d) : "f"(a), "f"(c));
    return d;
}

// Persistent fused kernel, 3 CTAs/SM (48 warps) for issue-rate headroom.
// CTA = (batch, pred-half, balanced gt-chunk). Per eval:
//   t = ||g||^2 - 2 g.p  (3 FFMA seeded with gw)
//   row-min: mn[q]=min(mn[q],t)  (+rp at emit; global atomicMax key merge)
//   col-min: ca  =min(ca, t*1+rp) (imm-FFMA; redux -> lane0 atomicMax key merge)
// Grid barrier (all 444 CTAs co-resident by __launch_bounds__(512,3)), then
// distributed fold of both key arrays + KL; ticket-last CTA writes out[0].
__global__ __launch_bounds__(THREADS, 3)
void chamfer_fused(const float* __restrict__ preds,
                   const float* __restrict__ gts,
                   const float* __restrict__ mu,
                   const float* __restrict__ logvar,
                   float* __restrict__ out)
{
    __shared__ float4 sg[GTSMAX];           // (-2gx, -2gy, -2gz, ||g||^2)
    __shared__ float  red[THREADS];
    __shared__ int    slast;

    // Balanced assignment: 32 groups (batch x half); groups 0-27 -> 14 chunks,
    // groups 28-31 -> 13 chunks. 28*14 + 4*13 = 444.
    const int cta = blockIdx.x;
    int grp, idx, C;
    if (cta < 392) { grp = cta / 14;              idx = cta % 14;         C = 14; }
    else           { grp = 28 + (cta - 392) / 13; idx = (cta - 392) % 13; C = 13; }
    const int batch = grp >> 1;
    const int half  = grp & 1;
    const int gA  = 2 * ((idx * (NN / 2)) / C);              // even start
    const int cnt = 2 * (((idx + 1) * (NN / 2)) / C) - gA;   // even, <= 316

    const int tid   = threadIdx.x;
    const bool lane0 = (tid & 31) == 0;

    // Stage this CTA's gt chunk (coalesced per-channel loads, pre-scale by -2)
    {
        const float* __restrict__ gb = gts + batch * 3 * NN;
        for (int i = tid; i < cnt; i += THREADS) {
            const int n = gA + i;
            const float x0 = gb[n];
            const float x1 = gb[NN + n];
            const float x2 = gb[2 * NN + n];
            sg[i] = make_float4(-2.0f * x0, -2.0f * x1, -2.0f * x2,
                                x0 * x0 + x1 * x1 + x2 * x2);
        }
    }

    // This thread's 4 preds (from its half) in registers
    float px[Q], py[Q], pz[Q], rp[Q], mn[Q];
    {
        const float* __restrict__ pb = preds + batch * 3 * NN;
#pragma unroll
        for (int q = 0; q < Q; q++) {
            const int m = half * HALF + tid + q * THREADS;
            px[q] = pb[m];
            py[q] = pb[NN + m];
            pz[q] = pb[2 * NN + m];
            rp[q] = px[q] * px[q] + py[q] * py[q] + pz[q] * pz[q];
            mn[q] = 3.4e38f;
        }
    }
    __syncthreads();

    // Main sweep, 2 gts per iteration; col-min merged straight to L2 keys.
    {
        unsigned* __restrict__ cm = g_cmkey + batch * NN + gA;
        for (int j = 0; j < cnt; j += 2) {
            const float4 g0 = sg[j];
            const float4 g1 = sg[j + 1];
            float ca0 = 3.4e38f, ca1 = 3.4e38f;
#pragma unroll
            for (int q = 0; q < Q; q += 2) {
                float t00 = fmaf(g0.x, px[q],   fmaf(g0.y, py[q],   fmaf(g0.z, pz[q],   g0.w)));
                float t01 = fmaf(g0.x, px[q+1], fmaf(g0.y, py[q+1], fmaf(g0.z, pz[q+1], g0.w)));
                float t10 = fmaf(g1.x, px[q],   fmaf(g1.y, py[q],   fmaf(g1.z, pz[q],   g1.w)));
                float t11 = fmaf(g1.x, px[q+1], fmaf(g1.y, py[q+1], fmaf(g1.z, pz[q+1], g1.w)));
                mn[q]   = fminf(mn[q],   fminf(t00, t10));
                mn[q+1] = fminf(mn[q+1], fminf(t01, t11));
                ca0 = fminf(ca0, fma_i1(t00, rp[q]));
                ca0 = fminf(ca0, fma_i1(t01, rp[q+1]));
                ca1 = fminf(ca1, fma_i1(t10, rp[q]));
                ca1 = fminf(ca1, fma_i1(t11, rp[q+1]));
            }
            const unsigned k0 = warp_redux_max(enc_min(ca0));
            const unsigned k1 = warp_redux_max(enc_min(ca1));
            if (lane0) {
                atomicMax(&cm[j],     k0);
                atomicMax(&cm[j + 1], k1);
            }
        }
    }

    // Merge partial row-mins across gt-chunks: encoded atomicMax.
    {
        const int pbase = batch * NN + half * HALF + tid;
#pragma unroll
        for (int q = 0; q < Q; q++)
            atomicMax(&g_rmkey[pbase + q * THREADS], enc_min(mn[q] + rp[q]));
    }

    // ---- Grid barrier: all 444 CTAs co-resident (3/SM x 148, by launch bounds)
    __syncthreads();
    if (tid == 0) {
        __threadfence();                       // order atomics before ticket
        atomicAdd(&g_c1, 1);
        while (*(volatile int*)&g_c1 < NCTA) __nanosleep(64);
    }
    __syncthreads();
    __threadfence();                           // acquire: keys stable in L2

    // ---- Phase 2: distributed fold of BOTH key arrays + KL, reset keys ----
    float f = 0.0f;
    {
        const int bx = blockIdx.x;
        const int ks = (bx * NKEYS) / NCTA;
        const int ke = ((bx + 1) * NKEYS) / NCTA;
        for (int i = ks + tid; i < ke; i += THREADS) {
            f += dec_min(__ldcg(&g_rmkey[i])) + dec_min(__ldcg(&g_cmkey[i]));
            g_rmkey[i] = 0u;                   // zero == +inf identity
            g_cmkey[i] = 0u;
        }
        const int zs = (bx * (BB * ZZ)) / NCTA;
        const int ze = ((bx + 1) * (BB * ZZ)) / NCTA;
        for (int i = zs + tid; i < ze; i += THREADS) {
            const float mm = mu[i];
            const float lv = logvar[i];
            f += -0.5f * (1.0f + lv - mm * mm - expf(lv));
        }
    }

    red[tid] = f;
    __syncthreads();
    for (int off = THREADS / 2; off > 0; off >>= 1) {
        if (tid < off) red[tid] += red[tid + off];
        __syncthreads();
    }

    if (tid == 0) {
        slast = 0;
        g_part2[blockIdx.x] = red[0];
        __threadfence();
        if (atomicAdd(&g_c2, 1) == NCTA - 1) slast = 1;
    }
    __syncthreads();

    // ---- Last CTA: final fold + write + ticket reset ----
    if (slast) {
        __threadfence();
        float t = 0.0f;
        for (int i = tid; i < NCTA; i += THREADS) t += __ldcg((float*)&g_part2[i]);
        red[tid] = t;
        __syncthreads();
        for (int off = THREADS / 2; off > 0; off >>= 1) {
            if (tid < off) red[tid] += red[tid + off];
            __syncthreads();
        }
        if (tid == 0) {
            out[0] = red[0];
            g_c1 = 0;          // reset tickets for next graph replay
            g_c2 = 0;
        }
    }
}

extern "C" void kernel_launch(void* const* d_in, const int* in_sizes, int n_in,
                              void* d_out, int out_size)
{
    const float* preds  = (const float*)d_in[0];   // [16, 3, 4096]
    const float* gts    = (const float*)d_in[1];   // [16, 3, 4096]
    const float* mu     = (const float*)d_in[2];   // [16, 128]
    const float* logvar = (const float*)d_in[3];   // [16, 128]
    float* out = (float*)d_out;

    chamfer_fused<<<NCTA, THREADS>>>(preds, gts, mu, logvar, out);
}

// round 13
// speedup vs baseline: 1.3572x; 1.3572x over previous
#include <cuda_runtime.h>
#include <math.h>

// Problem constants (fixed by the reference: B=16, N=4096, Z=128)
#define BB 16
#define NN 4096
#define ZZ 128

#define THREADS 512
#define Q 8                     // preds per thread: 512*8 = 4096 = ALL preds of the batch
#define NCTA 296                // 2 CTAs/SM on 148 SMs: all co-resident -> grid barrier safe
#define GTSMAX 232              // max gt-chunk (<=228 actual, padded)
#define NWARPS (THREADS / 32)   // 16
#define NKEYS (BB * NN)         // 65536

// Encoded row-min keys: zero-init == identity for atomicMax == +inf in min-space.
__device__ unsigned g_rmkey[NKEYS];     // 256KB, L2-resident
__device__ float    g_part2[NCTA];
__device__ int      g_c1 = 0;
__device__ int      g_c2 = 0;

// Monotone-DECREASING float->uint map (min(v) <=> max(key)), identity 0.
__device__ __forceinline__ unsigned enc_min(float v) {
    unsigned b = __float_as_uint(v);
    return (b & 0x80000000u) ? b : (~b & 0x7FFFFFFFu);
}
__device__ __forceinline__ float dec_min(unsigned m) {
    return __uint_as_float((m & 0x80000000u) ? m : (~m & 0x7FFFFFFFu));
}

// Warp-wide max reduction in ONE instruction.
__device__ __forceinline__ unsigned warp_redux_max(unsigned v) {
    unsigned r;
    asm("redux.sync.max.u32 %0, %1, 0xffffffff;" : "=r"(r) : "r"(v));
    return r;
}

// FFMA with immediate 1.0 multiplier: rt_SMSP=1
__device__ __forceinline__ float fma_i1(float a, float c) {
    float d;
    asm("fma.rn.f32 %0, %1, 0f3F800000, %2;" : "=f"(d) : "f"(a), "f"(c));
    return d;
}

__global__ __launch_bounds__(THREADS, 2)
void chamfer_fused(const float* __restrict__ preds,
                   const float* __restrict__ gts,
                   const float* __restrict__ mu,
                   const float* __restrict__ logvar,
                   float* __restrict__ out)
{
    __shared__ float4   sg[GTSMAX];             // (-2gx, -2gy, -2gz, ||g||^2)
    __shared__ unsigned scol[NWARPS * GTSMAX];  // per-warp col-min KEYS
    __shared__ float    red[THREADS];
    __shared__ int      slast;

    // Balanced (batch, chunk) assignment: batches 0-7 -> 19 CTAs, 8-15 -> 18.
    const int cta = blockIdx.x;
    int batch, idx, C;
    if (cta < 152) { batch = cta / 19;            idx = cta % 19;        C = 19; }
    else           { batch = 8 + (cta - 152) / 18; idx = (cta - 152) % 18; C = 18; }
    const int gA  = 2 * ((idx * (NN / 2)) / C);              // even start
    const int cnt = 2 * (((idx + 1) * (NN / 2)) / C) - gA;   // even, <= 228

    const float* __restrict__ pb = preds + batch * 3 * NN;

    const int tid   = threadIdx.x;
    const int wid   = tid >> 5;
    const bool lane0 = (tid & 31) == 0;

    // Stage this CTA's gt chunk (coalesced per-channel loads, pre-scale by -2)
    {
        const float* __restrict__ gb = gts + batch * 3 * NN;
        for (int i = tid; i < cnt; i += THREADS) {
            const int n = gA + i;
            const float x0 = gb[n];
            const float x1 = gb[NN + n];
            const float x2 = gb[2 * NN + n];
            sg[i] = make_float4(-2.0f * x0, -2.0f * x1, -2.0f * x2,
                                x0 * x0 + x1 * x1 + x2 * x2);
        }
    }

    // This thread's 8 preds in registers
    float px[Q], py[Q], pz[Q], rp[Q], mn[Q];
#pragma unroll
    for (int q = 0; q < Q; q++) {
        const int m = tid + q * THREADS;
        px[q] = pb[m];
        py[q] = pb[NN + m];
        pz[q] = pb[2 * NN + m];
        rp[q] = px[q] * px[q] + py[q] * py[q] + pz[q] * pz[q];
        mn[q] = 3.4e38f;
    }
    __syncthreads();

    // Main sweep, 2 gts per iteration. Col-min keys stored one iteration late
    // (software pipeline). Col accumulators split 4-way so each FMNMX chain is
    // only 4 deep (vs 8) — the longest serial chain in the body.
    {
        unsigned* __restrict__ sc = scol + wid * GTSMAX;
        unsigned kp0 = 0u, kp1 = 0u;
        for (int j = 0; j < cnt; j += 2) {
            if (lane0 && j > 0) {          // store previous pair's keys
                sc[j - 2] = kp0;
                sc[j - 1] = kp1;
            }
            const float4 g0 = sg[j];
            const float4 g1 = sg[j + 1];
            float ca0a = 3.4e38f, ca0b = 3.4e38f;
            float ca1a = 3.4e38f, ca1b = 3.4e38f;
#pragma unroll
            for (int q = 0; q < Q; q += 2) {
                float t00 = fmaf(g0.x, px[q],   fmaf(g0.y, py[q],   fmaf(g0.z, pz[q],   g0.w)));
                float t01 = fmaf(g0.x, px[q+1], fmaf(g0.y, py[q+1], fmaf(g0.z, pz[q+1], g0.w)));
                float t10 = fmaf(g1.x, px[q],   fmaf(g1.y, py[q],   fmaf(g1.z, pz[q],   g1.w)));
                float t11 = fmaf(g1.x, px[q+1], fmaf(g1.y, py[q+1], fmaf(g1.z, pz[q+1], g1.w)));
                mn[q]   = fminf(mn[q],   fminf(t00, t10));
                mn[q+1] = fminf(mn[q+1], fminf(t01, t11));
                ca0a = fminf(ca0a, fma_i1(t00, rp[q]));
                ca0b = fminf(ca0b, fma_i1(t01, rp[q+1]));
                ca1a = fminf(ca1a, fma_i1(t10, rp[q]));
                ca1b = fminf(ca1b, fma_i1(t11, rp[q+1]));
            }
            kp0 = warp_redux_max(enc_min(fminf(ca0a, ca0b)));
            kp1 = warp_redux_max(enc_min(fminf(ca1a, ca1b)));
        }
        if (lane0) {                       // drain the pipeline
            sc[cnt - 2] = kp0;
            sc[cnt - 1] = kp1;
        }
    }

    // Merge partial row-mins across gt-chunks: encoded atomicMax (exact,
    // order-independent). Spread addresses, coalesced lanes.
#pragma unroll
    for (int q = 0; q < Q; q++) {
        const int p = tid + q * THREADS;
        atomicMax(&g_rmkey[batch * NN + p], enc_min(mn[q] + rp[q]));
    }

    __syncthreads();

    // Cross-warp col-min reduce (integer max on keys) + sum over this CTA's gts
    float s = 0.0f;
    for (int i = tid; i < cnt; i += THREADS) {
        unsigned c = scol[i];
#pragma unroll
        for (int w = 1; w < NWARPS; w++)
            c = max(c, scol[w * GTSMAX + i]);
        s += dec_min(c);
    }
    red[tid] = s;
    __syncthreads();
    for (int off = THREADS / 2; off > 0; off >>= 1) {
        if (tid < off) red[tid] += red[tid + off];
        __syncthreads();
    }
    // red[0] holds this CTA's col-min sum; stays in smem across the barrier.

    // ---- Grid barrier: all 296 CTAs are co-resident (2/SM x 148) ----
    if (tid == 0) {
        __threadfence();                       // order atomicMax before ticket
        atomicAdd(&g_c1, 1);
        while (*(volatile int*)&g_c1 < NCTA) __nanosleep(64);
    }
    __syncthreads();
    __threadfence();                           // acquire: keys now stable in L2

    // ---- Phase 2: distributed fold (balanced slices), reset keys ----
    float f = 0.0f;
    {
        const int bx = blockIdx.x;             // recompute slices (no live regs)
        const int ks = (bx * NKEYS) / NCTA;
        const int ke = ((bx + 1) * NKEYS) / NCTA;
        for (int i = ks + tid; i < ke; i += THREADS) {
            f += dec_min(__ldcg(&g_rmkey[i]));
            g_rmkey[i] = 0u;                   // zero == +inf identity
        }
        const int zs = (bx * (BB * ZZ)) / NCTA;
        const int ze = ((bx + 1) * (BB * ZZ)) / NCTA;
        for (int i = zs + tid; i < ze; i += THREADS) {
            const float mm = mu[i];
            const float lv = logvar[i];
            f += -0.5f * (1.0f + lv - mm * mm - expf(lv));
        }
    }
    if (tid == 0) f += red[0];                 // fold own col-min sum (from smem)
    __syncthreads();                           // red[0] consumed before overwrite

    red[tid] = f;
    __syncthreads();
    for (int off = THREADS / 2; off > 0; off >>= 1) {
        if (tid < off) red[tid] += red[tid + off];
        __syncthreads();
    }

    if (tid == 0) {
        slast = 0;
        g_part2[blockIdx.x] = red[0];
        __threadfence();
        if (atomicAdd(&g_c2, 1) == NCTA - 1) slast = 1;
    }
    __syncthreads();

    // ---- Last CTA: final fold + write + ticket reset ----
    if (slast) {
        __threadfence();
        float t = 0.0f;
        for (int i = tid; i < NCTA; i += THREADS) t += __ldcg((float*)&g_part2[i]);
        red[tid] = t;
        __syncthreads();
        for (int off = THREADS / 2; off > 0; off >>= 1) {
            if (tid < off) red[tid] += red[tid + off];
            __syncthreads();
        }
        if (tid == 0) {
            out[0] = red[0];
            g_c1 = 0;          // reset tickets for next graph replay
            g_c2 = 0;
        }
    }
}

extern "C" void kernel_launch(void* const* d_in, const int* in_sizes, int n_in,
                              void* d_out, int out_size)
{
    const float* preds  = (const float*)d_in[0];   // [16, 3, 4096]
    const float* gts    = (const float*)d_in[1];   // [16, 3, 4096]
    const float* mu     = (const float*)d_in[2];   // [16, 128]
    const float* logvar = (const float*)d_in[3];   // [16, 128]
    float* out = (float*)d_out;

    chamfer_fused<<<NCTA, THREADS>>>(preds, gts, mu, logvar, out);
}

// round 14
// speedup vs baseline: 1.4738x; 1.0859x over previous
#include <cuda_runtime.h>
#include <math.h>

// Problem constants (fixed by the reference: B=16, N=4096, Z=128)
#define BB 16
#define NN 4096
#define ZZ 128

#define THREADS 512
#define Q 8                     // preds per thread: 512*8 = 4096 = ALL preds of the batch
#define NCTA 296                // 2 CTAs/SM on 148 SMs: all co-resident -> grid barrier safe
#define GTSMAX 232              // max gt-chunk (<=228 actual, padded)
#define NWARPS (THREADS / 32)   // 16
#define NKEYS (BB * NN)         // 65536

// Encoded row-min keys: zero-init == identity for atomicMax == +inf in min-space.
__device__ unsigned g_rmkey[NKEYS];     // 256KB, L2-resident
__device__ float    g_part2[NCTA];
__device__ int      g_c1 = 0;
__device__ int      g_c2 = 0;

// Full monotone-DECREASING float->uint map (min(v) <=> max(key)), identity 0.
// Used on the row path (safe for any sign).
__device__ __forceinline__ unsigned enc_min(float v) {
    unsigned b = __float_as_uint(v);
    return (b & 0x80000000u) ? b : (~b & 0x7FFFFFFFu);
}
__device__ __forceinline__ float dec_min(unsigned m) {
    return __uint_as_float((m & 0x80000000u) ? m : (~m & 0x7FFFFFFFu));
}

// CHEAP col-path encoding, valid for v >= 0 (true squared distances):
// key = ~bits is monotone decreasing on [0, +inf) -> single LOP.
__device__ __forceinline__ unsigned enc_nn(float v) {
    return ~__float_as_uint(v);
}
__device__ __forceinline__ float dec_nn(unsigned m) {
    return __uint_as_float(~m);
}

// Warp-wide max reduction in ONE instruction.
__device__ __forceinline__ unsigned warp_redux_max(unsigned v) {
    unsigned r;
    asm("redux.sync.max.u32 %0, %1, 0xffffffff;" : "=r"(r) : "r"(v));
    return r;
}

// FFMA with immediate 1.0 multiplier: rt_SMSP=1
__device__ __forceinline__ float fma_i1(float a, float c) {
    float d;
    asm("fma.rn.f32 %0, %1, 0f3F800000, %2;" : "=f"(d) : "f"(a), "f"(c));
    return d;
}

__global__ __launch_bounds__(THREADS, 2)
void chamfer_fused(const float* __restrict__ preds,
                   const float* __restrict__ gts,
                   const float* __restrict__ mu,
                   const float* __restrict__ logvar,
                   float* __restrict__ out)
{
    __shared__ float4   sg[GTSMAX];             // (-2gx, -2gy, -2gz, ||g||^2)
    __shared__ unsigned scol[NWARPS * GTSMAX];  // per-warp col-min KEYS (~bits)
    __shared__ float    red[THREADS];
    __shared__ int      slast;

    // Balanced (batch, chunk) assignment: batches 0-7 -> 19 CTAs, 8-15 -> 18.
    const int cta = blockIdx.x;
    int batch, idx, C;
    if (cta < 152) { batch = cta / 19;            idx = cta % 19;        C = 19; }
    else           { batch = 8 + (cta - 152) / 18; idx = (cta - 152) % 18; C = 18; }
    const int gA  = 2 * ((idx * (NN / 2)) / C);              // even start
    const int cnt = 2 * (((idx + 1) * (NN / 2)) / C) - gA;   // even, <= 228

    const float* __restrict__ pb = preds + batch * 3 * NN;

    const int tid   = threadIdx.x;
    const int wid   = tid >> 5;
    const bool lane0 = (tid & 31) == 0;

    // Stage this CTA's gt chunk (coalesced per-channel loads, pre-scale by -2)
    {
        const float* __restrict__ gb = gts + batch * 3 * NN;
        for (int i = tid; i < cnt; i += THREADS) {
            const int n = gA + i;
            const float x0 = gb[n];
            const float x1 = gb[NN + n];
            const float x2 = gb[2 * NN + n];
            sg[i] = make_float4(-2.0f * x0, -2.0f * x1, -2.0f * x2,
                                x0 * x0 + x1 * x1 + x2 * x2);
        }
    }

    // This thread's 8 preds in registers
    float px[Q], py[Q], pz[Q], rp[Q], mn[Q];
#pragma unroll
    for (int q = 0; q < Q; q++) {
        const int m = tid + q * THREADS;
        px[q] = pb[m];
        py[q] = pb[NN + m];
        pz[q] = pb[2 * NN + m];
        rp[q] = px[q] * px[q] + py[q] * py[q] + pz[q] * pz[q];
        mn[q] = 3.4e38f;
    }
    __syncthreads();

    // Main sweep, 2 gts per iteration. Warp col-min keys stored one iteration
    // LATE (software pipeline) so redux.sync latency overlaps compute.
    {
        unsigned* __restrict__ sc = scol + wid * GTSMAX;
        unsigned kp0 = 0u, kp1 = 0u;
        for (int j = 0; j < cnt; j += 2) {
            if (lane0 && j > 0) {          // store previous pair's keys
                sc[j - 2] = kp0;
                sc[j - 1] = kp1;
            }
            const float4 g0 = sg[j];
            const float4 g1 = sg[j + 1];
            float ca0 = 3.4e38f, ca1 = 3.4e38f;
#pragma unroll
            for (int q = 0; q < Q; q += 2) {
                float t00 = fmaf(g0.x, px[q],   fmaf(g0.y, py[q],   fmaf(g0.z, pz[q],   g0.w)));
                float t01 = fmaf(g0.x, px[q+1], fmaf(g0.y, py[q+1], fmaf(g0.z, pz[q+1], g0.w)));
                float t10 = fmaf(g1.x, px[q],   fmaf(g1.y, py[q],   fmaf(g1.z, pz[q],   g1.w)));
                float t11 = fmaf(g1.x, px[q+1], fmaf(g1.y, py[q+1], fmaf(g1.z, pz[q+1], g1.w)));
                mn[q]   = fminf(mn[q],   fminf(t00, t10));
                mn[q+1] = fminf(mn[q+1], fminf(t01, t11));
                ca0 = fminf(ca0, fma_i1(t00, rp[q]));
                ca0 = fminf(ca0, fma_i1(t01, rp[q+1]));
                ca1 = fminf(ca1, fma_i1(t10, rp[q]));
                ca1 = fminf(ca1, fma_i1(t11, rp[q+1]));
            }
            // ca0/ca1 are true squared distances (>= 0): single-NOT encoding.
            kp0 = warp_redux_max(enc_nn(ca0));
            kp1 = warp_redux_max(enc_nn(ca1));
        }
        if (lane0) {                       // drain the pipeline
            sc[cnt - 2] = kp0;
            sc[cnt - 1] = kp1;
        }
    }

    // Merge partial row-mins across gt-chunks: encoded atomicMax (full safe
    // encoding; exact, order-independent). Spread addresses, coalesced lanes.
#pragma unroll
    for (int q = 0; q < Q; q++) {
        const int p = tid + q * THREADS;
        atomicMax(&g_rmkey[batch * NN + p], enc_min(mn[q] + rp[q]));
    }

    __syncthreads();

    // Cross-warp col-min reduce (integer max on ~bits keys) + sum over gts
    float s = 0.0f;
    for (int i = tid; i < cnt; i += THREADS) {
        unsigned c = scol[i];
#pragma unroll
        for (int w = 1; w < NWARPS; w++)
            c = max(c, scol[w * GTSMAX + i]);
        s += dec_nn(c);
    }
    red[tid] = s;
    __syncthreads();
    for (int off = THREADS / 2; off > 0; off >>= 1) {
        if (tid < off) red[tid] += red[tid + off];
        __syncthreads();
    }
    // red[0] holds this CTA's col-min sum; stays in smem across the barrier.

    // ---- Grid barrier: all 296 CTAs are co-resident (2/SM x 148) ----
    if (tid == 0) {
        __threadfence();                       // order atomicMax before ticket
        atomicAdd(&g_c1, 1);
        while (*(volatile int*)&g_c1 < NCTA) __nanosleep(64);
    }
    __syncthreads();
    __threadfence();                           // acquire: keys now stable in L2

    // ---- Phase 2: distributed fold (balanced slices), reset keys ----
    float f = 0.0f;
    {
        const int bx = blockIdx.x;             // recompute slices (no live regs)
        const int ks = (bx * NKEYS) / NCTA;
        const int ke = ((bx + 1) * NKEYS) / NCTA;
        for (int i = ks + tid; i < ke; i += THREADS) {
            f += dec_min(__ldcg(&g_rmkey[i]));
            g_rmkey[i] = 0u;                   // zero == +inf identity
        }
        const int zs = (bx * (BB * ZZ)) / NCTA;
        const int ze = ((bx + 1) * (BB * ZZ)) / NCTA;
        for (int i = zs + tid; i < ze; i += THREADS) {
            const float mm = mu[i];
            const float lv = logvar[i];
            f += -0.5f * (1.0f + lv - mm * mm - expf(lv));
        }
    }
    if (tid == 0) f += red[0];                 // fold own col-min sum (from smem)
    __syncthreads();                           // red[0] consumed before overwrite

    red[tid] = f;
    __syncthreads();
    for (int off = THREADS / 2; off > 0; off >>= 1) {
        if (tid < off) red[tid] += red[tid + off];
        __syncthreads();
    }

    if (tid == 0) {
        slast = 0;
        g_part2[blockIdx.x] = red[0];
        __threadfence();
        if (atomicAdd(&g_c2, 1) == NCTA - 1) slast = 1;
    }
    __syncthreads();

    // ---- Last CTA: final fold + write + ticket reset ----
    if (slast) {
        __threadfence();
        float t = 0.0f;
        for (int i = tid; i < NCTA; i += THREADS) t += __ldcg((float*)&g_part2[i]);
        red[tid] = t;
        __syncthreads();
        for (int off = THREADS / 2; off > 0; off >>= 1) {
            if (tid < off) red[tid] += red[tid + off];
            __syncthreads();
        }
        if (tid == 0) {
            out[0] = red[0];
            g_c1 = 0;          // reset tickets for next graph replay
            g_c2 = 0;
        }
    }
}

extern "C" void kernel_launch(void* const* d_in, const int* in_sizes, int n_in,
                              void* d_out, int out_size)
{
    const float* preds  = (const float*)d_in[0];   // [16, 3, 4096]
    const float* gts    = (const float*)d_in[1];   // [16, 3, 4096]
    const float* mu     = (const float*)d_in[2];   // [16, 128]
    const float* logvar = (const float*)d_in[3];   // [16, 128]
    float* out = (float*)d_out;

    chamfer_fused<<<NCTA, THREADS>>>(preds, gts, mu, logvar, out);
}

// round 15
// speedup vs baseline: 1.5321x; 1.0396x over previous
#include <cuda_runtime.h>
#include <math.h>

// Problem constants (fixed by the reference: B=16, N=4096, Z=128)
#define BB 16
#define NN 4096
#define ZZ 128

#define THREADS 512
#define Q 8                     // preds per thread: 512*8 = 4096 = ALL preds of the batch
#define NCTA 296                // 2 CTAs/SM on 148 SMs: all co-resident -> grid barrier safe
#define GTSMAX 232              // max gt-chunk (<=228 actual, padded)
#define NWARPS (THREADS / 32)   // 16
#define NKEYS (BB * NN)         // 65536

// Encoded row-min keys: zero-init == identity for atomicMax == +inf in min-space.
__device__ unsigned g_rmkey[NKEYS];     // 256KB, L2-resident
__device__ float    g_part2[NCTA];
__device__ int      g_c1 = 0;
__device__ int      g_c2 = 0;

// Full monotone-DECREASING float->uint map (min(v) <=> max(key)), identity 0.
__device__ __forceinline__ unsigned enc_min(float v) {
    unsigned b = __float_as_uint(v);
    return (b & 0x80000000u) ? b : (~b & 0x7FFFFFFFu);
}
__device__ __forceinline__ float dec_min(unsigned m) {
    return __uint_as_float((m & 0x80000000u) ? m : (~m & 0x7FFFFFFFu));
}

// CHEAP encoding for v >= 0 (true squared distances): key = ~bits, single LOP.
__device__ __forceinline__ unsigned enc_nn(float v) {
    return ~__float_as_uint(v);
}
__device__ __forceinline__ float dec_nn(unsigned m) {
    return __uint_as_float(~m);
}

// Warp-wide max reduction in ONE instruction.
__device__ __forceinline__ unsigned warp_redux_max(unsigned v) {
    unsigned r;
    asm("redux.sync.max.u32 %0, %1, 0xffffffff;" : "=r"(r) : "r"(v));
    return r;
}

// FFMA with immediate 1.0 multiplier: rt_SMSP=1
__device__ __forceinline__ float fma_i1(float a, float c) {
    float d;
    asm("fma.rn.f32 %0, %1, 0f3F800000, %2;" : "=f"(d) : "f"(a), "f"(c));
    return d;
}

// Persistent fused kernel (converged structure from R11/R14).
// Phase 1: CTA = (batch, balanced gt-chunk), ALL 4096 preds in registers.
//   t' = (||g||^2 + ||p||^2) - 2 g.p = P[j,q]  (imm-FFMA seed + 3 FFMA)
//   row-min: mn[q] = min(mn[q], t')  -> global atomicMax key merge (exact)
//   col-min: ca    = min(ca,   t')  -> redux.sync key, stored one iter late
// Grid barrier (all 296 CTAs co-resident), distributed fold + KL, ticket-last
// CTA writes out[0]. One launch total.
__global__ __launch_bounds__(THREADS, 2)
void chamfer_fused(const float* __restrict__ preds,
                   const float* __restrict__ gts,
                   const float* __restrict__ mu,
                   const float* __restrict__ logvar,
                   float* __restrict__ out)
{
    __shared__ float4   sg[GTSMAX];             // (-2gx, -2gy, -2gz, ||g||^2)
    __shared__ unsigned scol[NWARPS * GTSMAX];  // per-warp col-min KEYS (~bits)
    __shared__ float    red[THREADS];
    __shared__ int      slast;

    // Balanced (batch, chunk) assignment: batches 0-7 -> 19 CTAs, 8-15 -> 18.
    const int cta = blockIdx.x;
    int batch, idx, C;
    if (cta < 152) { batch = cta / 19;            idx = cta % 19;        C = 19; }
    else           { batch = 8 + (cta - 152) / 18; idx = (cta - 152) % 18; C = 18; }
    const int gA  = 2 * ((idx * (NN / 2)) / C);              // even start
    const int cnt = 2 * (((idx + 1) * (NN / 2)) / C) - gA;   // even, <= 228

    const float* __restrict__ pb = preds + batch * 3 * NN;

    const int tid   = threadIdx.x;
    const int wid   = tid >> 5;
    const bool lane0 = (tid & 31) == 0;

    // Stage this CTA's gt chunk (coalesced per-channel loads, pre-scale by -2)
    {
        const float* __restrict__ gb = gts + batch * 3 * NN;
        for (int i = tid; i < cnt; i += THREADS) {
            const int n = gA + i;
            const float x0 = gb[n];
            const float x1 = gb[NN + n];
            const float x2 = gb[2 * NN + n];
            sg[i] = make_float4(-2.0f * x0, -2.0f * x1, -2.0f * x2,
                                x0 * x0 + x1 * x1 + x2 * x2);
        }
    }

    // This thread's 8 preds in registers
    float px[Q], py[Q], pz[Q], rp[Q], mn[Q];
#pragma unroll
    for (int q = 0; q < Q; q++) {
        const int m = tid + q * THREADS;
        px[q] = pb[m];
        py[q] = pb[NN + m];
        pz[q] = pb[2 * NN + m];
        rp[q] = px[q] * px[q] + py[q] * py[q] + pz[q] * pz[q];
        mn[q] = 3.4e38f;
    }
    __syncthreads();

    // Main sweep, 2 gts per iteration. The rp term is folded into the FFMA
    // seed, so t' = P[j,q] feeds BOTH mins directly (no post-dot imm-FFMA on
    // the critical path). Col keys stored one iteration late (pipelined).
    {
        unsigned* __restrict__ sc = scol + wid * GTSMAX;
        unsigned kp0 = 0u, kp1 = 0u;
        for (int j = 0; j < cnt; j += 2) {
            if (lane0 && j > 0) {          // store previous pair's keys
                sc[j - 2] = kp0;
                sc[j - 1] = kp1;
            }
            const float4 g0 = sg[j];
            const float4 g1 = sg[j + 1];
            float ca0 = 3.4e38f, ca1 = 3.4e38f;
#pragma unroll
            for (int q = 0; q < Q; q += 2) {
                const float s0a = fma_i1(g0.w, rp[q]);     // seeds: off critical path
                const float s0b = fma_i1(g0.w, rp[q+1]);
                const float s1a = fma_i1(g1.w, rp[q]);
                const float s1b = fma_i1(g1.w, rp[q+1]);
                float t00 = fmaf(g0.x, px[q],   fmaf(g0.y, py[q],   fmaf(g0.z, pz[q],   s0a)));
                float t01 = fmaf(g0.x, px[q+1], fmaf(g0.y, py[q+1], fmaf(g0.z, pz[q+1], s0b)));
                float t10 = fmaf(g1.x, px[q],   fmaf(g1.y, py[q],   fmaf(g1.z, pz[q],   s1a)));
                float t11 = fmaf(g1.x, px[q+1], fmaf(g1.y, py[q+1], fmaf(g1.z, pz[q+1], s1b)));
                mn[q]   = fminf(mn[q],   fminf(t00, t10));
                mn[q+1] = fminf(mn[q+1], fminf(t01, t11));
                ca0 = fminf(ca0, fminf(t00, t01));
                ca1 = fminf(ca1, fminf(t10, t11));
            }
            // ca0/ca1 are true squared distances (>= 0): single-NOT encoding.
            kp0 = warp_redux_max(enc_nn(ca0));
            kp1 = warp_redux_max(enc_nn(ca1));
        }
        if (lane0) {                       // drain the pipeline
            sc[cnt - 2] = kp0;
            sc[cnt - 1] = kp1;
        }
    }

    // Merge partial row-mins across gt-chunks: encoded atomicMax (full safe
    // encoding; exact, order-independent). mn already includes rp (it is P).
#pragma unroll
    for (int q = 0; q < Q; q++) {
        const int p = tid + q * THREADS;
        atomicMax(&g_rmkey[batch * NN + p], enc_min(mn[q]));
    }

    __syncthreads();

    // Cross-warp col-min reduce (integer max on ~bits keys) + sum over gts
    float s = 0.0f;
    for (int i = tid; i < cnt; i += THREADS) {
        unsigned c = scol[i];
#pragma unroll
        for (int w = 1; w < NWARPS; w++)
            c = max(c, scol[w * GTSMAX + i]);
        s += dec_nn(c);
    }
    red[tid] = s;
    __syncthreads();
    for (int off = THREADS / 2; off > 0; off >>= 1) {
        if (tid < off) red[tid] += red[tid + off];
        __syncthreads();
    }
    // red[0] holds this CTA's col-min sum; stays in smem across the barrier.

    // ---- Grid barrier: all 296 CTAs are co-resident (2/SM x 148) ----
    if (tid == 0) {
        __threadfence();                       // order atomicMax before ticket
        atomicAdd(&g_c1, 1);
        while (*(volatile int*)&g_c1 < NCTA) __nanosleep(64);
    }
    __syncthreads();
    __threadfence();                           // acquire: keys now stable in L2

    // ---- Phase 2: distributed fold (balanced slices), reset keys ----
    float f = 0.0f;
    {
        const int bx = blockIdx.x;             // recompute slices (no live regs)
        const int ks = (bx * NKEYS) / NCTA;
        const int ke = ((bx + 1) * NKEYS) / NCTA;
        for (int i = ks + tid; i < ke; i += THREADS) {
            f += dec_min(__ldcg(&g_rmkey[i]));
            g_rmkey[i] = 0u;                   // zero == +inf identity
        }
        const int zs = (bx * (BB * ZZ)) / NCTA;
        const int ze = ((bx + 1) * (BB * ZZ)) / NCTA;
        for (int i = zs + tid; i < ze; i += THREADS) {
            const float mm = mu[i];
            const float lv = logvar[i];
            f += -0.5f * (1.0f + lv - mm * mm - expf(lv));
        }
    }
    if (tid == 0) f += red[0];                 // fold own col-min sum (from smem)
    __syncthreads();                           // red[0] consumed before overwrite

    red[tid] = f;
    __syncthreads();
    for (int off = THREADS / 2; off > 0; off >>= 1) {
        if (tid < off) red[tid] += red[tid + off];
        __syncthreads();
    }

    if (tid == 0) {
        slast = 0;
        g_part2[blockIdx.x] = red[0];
        __threadfence();
        if (atomicAdd(&g_c2, 1) == NCTA - 1) slast = 1;
    }
    __syncthreads();

    // ---- Last CTA: final fold + write + ticket reset ----
    if (slast) {
        __threadfence();
        float t = 0.0f;
        for (int i = tid; i < NCTA; i += THREADS) t += __ldcg((float*)&g_part2[i]);
        red[tid] = t;
        __syncthreads();
        for (int off = THREADS / 2; off > 0; off >>= 1) {
            if (tid < off) red[tid] += red[tid + off];
            __syncthreads();
        }
        if (tid == 0) {
            out[0] = red[0];
            g_c1 = 0;          // reset tickets for next graph replay
            g_c2 = 0;
        }
    }
}

extern "C" void kernel_launch(void* const* d_in, const int* in_sizes, int n_in,
                              void* d_out, int out_size)
{
    const float* preds  = (const float*)d_in[0];   // [16, 3, 4096]
    const float* gts    = (const float*)d_in[1];   // [16, 3, 4096]
    const float* mu     = (const float*)d_in[2];   // [16, 128]
    const float* logvar = (const float*)d_in[3];   // [16, 128]
    float* out = (float*)d_out;

    chamfer_fused<<<NCTA, THREADS>>>(preds, gts, mu, logvar, out);
}